// round 16
// baseline (speedup 1.0000x reference)
#include <cuda_runtime.h>
#include <cuda_fp16.h>
#include <cstdint>
#include <cstddef>

#define S_LEN 2048
#define BATCH 4
#define DIM   1024
#define MQKV  (BATCH * S_LEN)   // 8192

// ---------------------------------------------------------------------------
// scratch (static device globals; no allocation in kernel_launch)
// ---------------------------------------------------------------------------
#define DEVH(name, n) __device__ __align__(256) __half name[n]
DEVH(g_xh,  (size_t)MQKV * DIM);
DEVH(g_wqh, (size_t)DIM * DIM);
DEVH(g_wkh, (size_t)DIM * DIM);
DEVH(g_wvh, (size_t)DIM * DIM);
DEVH(g_qh,  (size_t)MQKV * DIM);
DEVH(g_kh,  (size_t)MQKV * DIM);
DEVH(g_vh,  (size_t)MQKV * DIM);
DEVH(g_sch, (size_t)BATCH * S_LEN * S_LEN);   // scores, fp16
DEVH(g_ph,  (size_t)BATCH * S_LEN * S_LEN);   // probs, fp16

// ---------------------------------------------------------------------------
// PTX helpers — non-'a'-suffix ISA only (cp.async, ldmatrix, mma.sync).
// ---------------------------------------------------------------------------
__device__ __forceinline__ uint32_t smem_to_u32(const void* p) {
    uint32_t a;
    asm("{ .reg .u64 t; cvta.to.shared.u64 t, %1; cvt.u32.u64 %0, t; }"
        : "=r"(a) : "l"(p));
    return a;
}
__device__ __forceinline__ void cp_async16(uint32_t s, const void* g) {
    asm volatile("cp.async.cg.shared.global [%0], [%1], 16;" :: "r"(s), "l"(g));
}
#define CP_COMMIT() asm volatile("cp.async.commit_group;" ::: "memory")
#define CP_WAIT(n)  asm volatile("cp.async.wait_group %0;" :: "n"(n) : "memory")

__device__ __forceinline__ void ldsm_x4(uint32_t* r, uint32_t addr) {
    asm volatile("ldmatrix.sync.aligned.m8n8.x4.shared.b16 {%0,%1,%2,%3}, [%4];"
        : "=r"(r[0]), "=r"(r[1]), "=r"(r[2]), "=r"(r[3]) : "r"(addr));
}
__device__ __forceinline__ void ldsm_x4_t(uint32_t* r, uint32_t addr) {
    asm volatile("ldmatrix.sync.aligned.m8n8.x4.trans.shared.b16 {%0,%1,%2,%3}, [%4];"
        : "=r"(r[0]), "=r"(r[1]), "=r"(r[2]), "=r"(r[3]) : "r"(addr));
}
__device__ __forceinline__ void mma16816(float* c, const uint32_t* a,
                                         uint32_t b0, uint32_t b1) {
    asm volatile(
        "mma.sync.aligned.m16n8k16.row.col.f32.f16.f16.f32 "
        "{%0,%1,%2,%3}, {%4,%5,%6,%7}, {%8,%9}, {%0,%1,%2,%3};"
        : "+f"(c[0]), "+f"(c[1]), "+f"(c[2]), "+f"(c[3])
        : "r"(a[0]), "r"(a[1]), "r"(a[2]), "r"(a[3]), "r"(b0), "r"(b1));
}

// fast exp on the FMA pipe (no MUFU): exp(x) = 2^(x*log2e), deg-5 poly.
__device__ __forceinline__ float fexp(float x) {
    float t = fmaxf(x * 1.4426950408889634f, -126.0f);
    float n = rintf(t);
    float f = t - n;
    float p = 1.3333558146428443e-3f;
    p = fmaf(p, f, 9.6181291076284772e-3f);
    p = fmaf(p, f, 5.5504108664821580e-2f);
    p = fmaf(p, f, 2.4022650695910072e-1f);
    p = fmaf(p, f, 6.9314718055994531e-1f);
    p = fmaf(p, f, 1.0f);
    uint32_t sc = (uint32_t)((int)n + 127) << 23;
    return __uint_as_float(sc) * p;
}

// up to 3 operand/output sets, selected by blockIdx.z when zsel=1
struct G3 {
    const __half* Bh[3];
    const float*  bias[3];
    float*        Cf[3];
    __half*       Ch[3];
};

// ---------------------------------------------------------------------------
// fp16 GEMM (fp32 accumulate) on tensor cores.
//   TRANSB=0: C[m,n] = sum_k A[m,k] * B[n,k]   (NT; B row-major [n,k])
//   TRANSB=1: C[m,n] = sum_k A[m,k] * B[k,n]   (NN via ldmatrix.trans)
//   MT: CTA M-tile (128 -> 2x2 warps of 64x64; 64 -> 1x4 warps of 64x32).
// N-tile fixed 128, 128 threads, K-chunk 64, cp.async double buffer.
// MT=128: 2 CTAs/SM; MT=64: 4 CTAs/SM (PV — doubles warps/SMSP, halves
// wave granularity).
// ---------------------------------------------------------------------------
#define ROW_A     144                // 64 fp16 = 128B data + 16B pad
#define ROW_BT    272                // 128 fp16 = 256B data + 16B pad (trans B)

template <int TRANSB, int MT>
__global__ __launch_bounds__(128, (MT == 64) ? 4 : 2)
void gemm_fp16(const __half* __restrict__ Ah,
               const G3 args,
               int M, int N, int K, float alpha,
               size_t sA, size_t sB, size_t sC, int zsel)
{
    constexpr int NFR   = (MT == 128) ? 8 : 4;        // n-frags per warp (x8)
    constexpr int JB    = NFR / 2;                    // B ldsm per kk
    constexpr uint32_t TILE_A_SZ = (uint32_t)MT * ROW_A;
    constexpr uint32_t TILE_B_SZ = TRANSB ? 64u * ROW_BT : 128u * ROW_A;
    constexpr uint32_t STAGE_SZ  = TILE_A_SZ + TILE_B_SZ;

    extern __shared__ __align__(16) char smem[];
    const uint32_t smem_u = smem_to_u32(smem);

    const int tid  = threadIdx.x;
    const int wid  = tid >> 5, lane = tid & 31;
    const int wm   = (MT == 128) ? (wid >> 1) : 0;
    const int wn   = (MT == 128) ? (wid & 1)  : wid;
    const int m0   = blockIdx.y * MT;
    const int n0   = blockIdx.x * 128;

    const int    zs = zsel ? (int)blockIdx.z : 0;
    const size_t zb = zsel ? 0 : (size_t)blockIdx.z;

    Ah += sA * zb;
    const __half* Bh = args.Bh[zs] + sB * zb;
    const float*  bias = args.bias[zs];
    float*        Cf = args.Cf[zs];
    __half*       Ch = args.Ch[zs];
    const size_t  co = sC * zb;

    // ---- loader ----
    auto load_stage = [&](int c, int s) {
        const int k0 = c * 64;
        const uint32_t st = smem_u + s * STAGE_SZ;
        #pragma unroll
        for (int h = 0; h < MT / 16; ++h) {          // A: MT*8 chunks
            int ci = tid + h * 128;
            int row = ci >> 3, col = ci & 7;
            cp_async16(st + row * ROW_A + col * 16,
                       Ah + (size_t)(m0 + row) * K + k0 + col * 8);
        }
        #pragma unroll
        for (int h = 0; h < 8; ++h) {                // B: 1024 chunks
            int ci = tid + h * 128;
            if (TRANSB == 0) {   // B row-major [n,k]: 128 rows x 8 chunks
                int row = ci >> 3, col = ci & 7;
                cp_async16(st + TILE_A_SZ + row * ROW_A + col * 16,
                           Bh + (size_t)(n0 + row) * K + k0 + col * 8);
            } else {             // B row-major [k,n]: 64 rows x 16 chunks
                int row = ci >> 4, col = ci & 15;
                cp_async16(st + TILE_A_SZ + row * ROW_BT + col * 16,
                           Bh + (size_t)(k0 + row) * N + n0 + col * 8);
            }
        }
        CP_COMMIT();
    };

    float acc[4][NFR][4];
    #pragma unroll
    for (int i = 0; i < 4; ++i)
        #pragma unroll
        for (int j = 0; j < NFR; ++j)
            #pragma unroll
            for (int e = 0; e < 4; ++e) acc[i][j][e] = 0.f;

    const int NC = K >> 6;             // K / 64
    load_stage(0, 0);

    const uint32_t aoff = (uint32_t)((wm * 64 + (lane & 15)) * ROW_A +
                                     ((lane & 16) ? 16 : 0));
    const uint32_t boff_nt = (uint32_t)((wn * (NFR * 8) + ((lane & 16) >> 1) + (lane & 7)) * ROW_A +
                                        ((lane & 8) ? 16 : 0));
    const uint32_t boff_t = (uint32_t)((((lane >> 3) & 1) * 8 + (lane & 7)) * ROW_BT +
                                       (wn * (NFR * 8) + (lane >> 4) * 8) * 2);

    for (int c = 0; c < NC; ++c) {
        if (c + 1 < NC) { load_stage(c + 1, (c + 1) & 1); CP_WAIT(1); }
        else            { CP_WAIT(0); }
        __syncthreads();

        const uint32_t st = smem_u + (c & 1) * STAGE_SZ;
        #pragma unroll
        for (int kk = 0; kk < 4; ++kk) {    // four k16 steps per chunk
            uint32_t bhf[JB][4];
            if (TRANSB == 0) {
                const uint32_t kb = kk * 32;            // 16 fp16 = 32 B
                #pragma unroll
                for (int j = 0; j < JB; ++j)
                    ldsm_x4(bhf[j], st + TILE_A_SZ + boff_nt + kb + j * (16 * ROW_A));
            } else {
                const uint32_t kb = kk * 16 * ROW_BT;   // 16 k-rows down
                #pragma unroll
                for (int j = 0; j < JB; ++j)
                    ldsm_x4_t(bhf[j], st + TILE_A_SZ + boff_t + kb + j * 32);
            }
            #pragma unroll
            for (int mi = 0; mi < 4; ++mi) {
                uint32_t ahf[4];
                ldsm_x4(ahf, st + aoff + kk * 32 + mi * (16 * ROW_A));
                #pragma unroll
                for (int nf = 0; nf < NFR; ++nf) {
                    const int j = nf >> 1, p = (nf & 1) * 2;
                    mma16816(acc[mi][nf], ahf, bhf[j][p], bhf[j][p + 1]);
                }
            }
        }
        __syncthreads();
    }

    // ---- epilogue ----
    const int r0 = lane >> 2;
    const int c0l = (lane & 3) * 2;
    #pragma unroll
    for (int mi = 0; mi < 4; ++mi) {
        #pragma unroll
        for (int nf = 0; nf < NFR; ++nf) {
            const int col  = n0 + wn * (NFR * 8) + nf * 8 + c0l;
            const int rowA = m0 + wm * 64 + mi * 16 + r0;
            float b0 = 0.f, b1 = 0.f;
            if (bias) { b0 = bias[col]; b1 = bias[col + 1]; }
            float v0 = fmaf(alpha, acc[mi][nf][0], b0);
            float v1 = fmaf(alpha, acc[mi][nf][1], b1);
            float v2 = fmaf(alpha, acc[mi][nf][2], b0);
            float v3 = fmaf(alpha, acc[mi][nf][3], b1);
            if (Cf) {
                float* p0 = Cf + co + (size_t)rowA * N + col;
                *(float2*)p0                     = make_float2(v0, v1);
                *(float2*)(p0 + (size_t)8 * N)   = make_float2(v2, v3);
            }
            if (Ch) {
                size_t o0 = co + (size_t)rowA * N + col;
                *(__half2*)(Ch + o0) =
                    __halves2half2(__float2half_rn(v0), __float2half_rn(v1));
                *(__half2*)(Ch + o0 + (size_t)8 * N) =
                    __halves2half2(__float2half_rn(v2), __float2half_rn(v3));
            }
        }
    }
}

#define SMEM_NT128 (2 * (128 * ROW_A + 128 * ROW_A))   // 73728
#define SMEM_NN64  (2 * (64 * ROW_A + 64 * ROW_BT))    // 53248

// ---------------------------------------------------------------------------
// fused conversions: blocks [0,8192) transpose-convert x; [8192,11264) convert
// the three weight matrices (1024 blocks each). One launch.
// ---------------------------------------------------------------------------
struct C4 { const float* x; __half* xh; const float* W[3]; __half* H[3]; };
__global__ __launch_bounds__(256) void conv_all(const C4 a) {
    int bid = blockIdx.x;
    if (bid < MQKV) {
        int b = bid / S_LEN, s = bid % S_LEN;
        float4 v = ((const float4*)(a.x + ((size_t)s * BATCH + b) * DIM))[threadIdx.x];
        size_t o = (size_t)bid * DIM + (size_t)threadIdx.x * 4;
        ((__half2*)(a.xh + o))[0] = __halves2half2(__float2half_rn(v.x),
                                                   __float2half_rn(v.y));
        ((__half2*)(a.xh + o))[1] = __halves2half2(__float2half_rn(v.z),
                                                   __float2half_rn(v.w));
    } else {
        int r = bid - MQKV;
        int w = r >> 10;                        // 0..2
        int i = (r & 1023) * 256 + threadIdx.x; // float4 index in 1024x1024
        float4 v = ((const float4*)a.W[w])[i];
        size_t o = (size_t)i * 4;
        ((__half2*)(a.H[w] + o))[0] = __halves2half2(__float2half_rn(v.x),
                                                     __float2half_rn(v.y));
        ((__half2*)(a.H[w] + o))[1] = __halves2half2(__float2half_rn(v.z),
                                                     __float2half_rn(v.w));
    }
}

// softmax over rows of sch (fp16, len S_LEN) -> fp16 probs.
__global__ __launch_bounds__(256) void softmax_h(const __half* __restrict__ sch,
                                                 __half* __restrict__ ph) {
    const int tid = threadIdx.x;
    const uint4* p = (const uint4*)(sch + (size_t)blockIdx.x * S_LEN);
    __shared__ float red[8];

    uint4 r = p[tid];
    float e[8];
    {
        __half2 h0 = *(__half2*)&r.x, h1 = *(__half2*)&r.y;
        __half2 h2 = *(__half2*)&r.z, h3 = *(__half2*)&r.w;
        float2 f0 = __half22float2(h0), f1 = __half22float2(h1);
        float2 f2 = __half22float2(h2), f3 = __half22float2(h3);
        e[0] = f0.x; e[1] = f0.y; e[2] = f1.x; e[3] = f1.y;
        e[4] = f2.x; e[5] = f2.y; e[6] = f3.x; e[7] = f3.y;
    }

    float lmax = e[0];
    #pragma unroll
    for (int i = 1; i < 8; ++i) lmax = fmaxf(lmax, e[i]);
    #pragma unroll
    for (int o = 16; o; o >>= 1) lmax = fmaxf(lmax, __shfl_xor_sync(~0u, lmax, o));
    if ((tid & 31) == 0) red[tid >> 5] = lmax;
    __syncthreads();
    float gmax = red[0];
    #pragma unroll
    for (int w = 1; w < 8; ++w) gmax = fmaxf(gmax, red[w]);
    __syncthreads();

    float lsum = 0.f;
    #pragma unroll
    for (int i = 0; i < 8; ++i) { e[i] = fexp(e[i] - gmax); lsum += e[i]; }
    #pragma unroll
    for (int o = 16; o; o >>= 1) lsum += __shfl_xor_sync(~0u, lsum, o);
    if ((tid & 31) == 0) red[tid >> 5] = lsum;
    __syncthreads();
    float gsum = 0.f;
    #pragma unroll
    for (int w = 0; w < 8; ++w) gsum += red[w];
    float inv = 1.f / gsum;

    uint4 o4;
    *(__half2*)&o4.x = __halves2half2(__float2half_rn(e[0] * inv),
                                      __float2half_rn(e[1] * inv));
    *(__half2*)&o4.y = __halves2half2(__float2half_rn(e[2] * inv),
                                      __float2half_rn(e[3] * inv));
    *(__half2*)&o4.z = __halves2half2(__float2half_rn(e[4] * inv),
                                      __float2half_rn(e[5] * inv));
    *(__half2*)&o4.w = __halves2half2(__float2half_rn(e[6] * inv),
                                      __float2half_rn(e[7] * inv));
    ((uint4*)(ph + (size_t)blockIdx.x * S_LEN))[tid] = o4;
}

// ---------------------------------------------------------------------------
extern "C" void kernel_launch(void* const* d_in, const int* in_sizes, int n_in,
                              void* d_out, int out_size) {
    const float* x  = (const float*)d_in[0];
    const float* Wq = (const float*)d_in[1];
    const float* bq = (const float*)d_in[2];
    const float* Wk = (const float*)d_in[3];
    const float* bk = (const float*)d_in[4];
    const float* Wv = (const float*)d_in[5];
    const float* bv = (const float*)d_in[6];
    float* out = (float*)d_out;

    cudaFuncSetAttribute((const void*)gemm_fp16<0, 128>,
                         cudaFuncAttributeMaxDynamicSharedMemorySize, SMEM_NT128);
    cudaFuncSetAttribute((const void*)gemm_fp16<1, 64>,
                         cudaFuncAttributeMaxDynamicSharedMemorySize, SMEM_NN64);

    __half *xh, *wqh, *wkh, *wvh, *qh, *kh, *vh, *sch, *ph;
    cudaGetSymbolAddress((void**)&xh, g_xh);
    cudaGetSymbolAddress((void**)&wqh, g_wqh);
    cudaGetSymbolAddress((void**)&wkh, g_wkh);
    cudaGetSymbolAddress((void**)&wvh, g_wvh);
    cudaGetSymbolAddress((void**)&qh, g_qh);
    cudaGetSymbolAddress((void**)&kh, g_kh);
    cudaGetSymbolAddress((void**)&vh, g_vh);
    cudaGetSymbolAddress((void**)&sch, g_sch);
    cudaGetSymbolAddress((void**)&ph, g_ph);

    // 1) fused input conversions (x + 3 weight matrices, one launch)
    {
        C4 c{};
        c.x = x; c.xh = xh;
        c.W[0] = Wq; c.W[1] = Wk; c.W[2] = Wv;
        c.H[0] = wqh; c.H[1] = wkh; c.H[2] = wvh;
        conv_all<<<MQKV + 3 * 1024, 256>>>(c);
    }

    // 2) fused QKV projections (NT; one launch, z selects weight set)
    {
        G3 a{};
        a.Bh[0] = wqh; a.Bh[1] = wkh; a.Bh[2] = wvh;
        a.bias[0] = bq; a.bias[1] = bk; a.bias[2] = bv;
        a.Ch[0] = qh; a.Ch[1] = kh; a.Ch[2] = vh;
        dim3 grid(DIM / 128, MQKV / 128, 3);
        gemm_fp16<0, 128><<<grid, 128, SMEM_NT128>>>(xh, a,
                                                     MQKV, DIM, DIM, 1.f, 0, 0, 0, 1);
    }

    // 3) scores = Q K^T / sqrt(D)  (NT) -> fp16
    {
        G3 a{};
        a.Bh[0] = kh; a.Ch[0] = sch;
        dim3 grid(S_LEN / 128, S_LEN / 128, BATCH);
        gemm_fp16<0, 128><<<grid, 128, SMEM_NT128>>>(qh, a,
                                                     S_LEN, S_LEN, DIM, 0.03125f,
                                                     (size_t)S_LEN * DIM, (size_t)S_LEN * DIM,
                                                     (size_t)S_LEN * S_LEN, 0);
    }

    // 4) softmax (fp16 in, fp16 out; FMA-pipe exp)
    softmax_h<<<BATCH * S_LEN, 256>>>(sch, ph);

    // 5) out = P V  (NN via ldmatrix.trans; M-tile 64 -> 1024 CTAs, 4 CTAs/SM)
    {
        G3 a{};
        a.Bh[0] = vh; a.Cf[0] = out;
        dim3 grid(DIM / 128, S_LEN / 64, BATCH);
        gemm_fp16<1, 64><<<grid, 128, SMEM_NN64>>>(ph, a,
                                                   S_LEN, DIM, S_LEN, 1.f,
                                                   (size_t)S_LEN * S_LEN, (size_t)S_LEN * DIM,
                                                   (size_t)S_LEN * DIM, 0);
    }
}